// round 2
// baseline (speedup 1.0000x reference)
#include <cuda_runtime.h>
#include <cstdint>

#define BS   128
#define HW   256
#define NPX  (HW * HW)          // 65536
#define NTOT (BS * NPX)         // 8,388,608

// Scratch: scatter keys (winner = max linear source index h*256+w) and per-batch
// valid-pixel counts for the all-True mask fallback.
__device__ int g_keys[NTOT];          // 33.5 MB
__device__ int g_nvalid[BS];

// ---------------------------------------------------------------------------
// k0: zero keys (vectorized) + counters
// ---------------------------------------------------------------------------
__global__ void k_zero() {
    int i = blockIdx.x * blockDim.x + threadIdx.x;
    int4* p = reinterpret_cast<int4*>(g_keys);
    if (i < NTOT / 4) p[i] = make_int4(0, 0, 0, 0);
    if (i < BS) g_nvalid[i] = 0;
}

// ---------------------------------------------------------------------------
// k1: per-batch count of seg > 0.5  (8 blocks per batch, 8192 px each)
// ---------------------------------------------------------------------------
__global__ void k_count(const float* __restrict__ seg) {
    int b    = blockIdx.x >> 3;
    int base = b * NPX + (blockIdx.x & 7) * 8192;
    const float4* s4 = reinterpret_cast<const float4*>(seg + base);
    int cnt = 0;
    #pragma unroll 4
    for (int i = threadIdx.x; i < 2048; i += 256) {
        float4 v = s4[i];
        cnt += (v.x > 0.5f) + (v.y > 0.5f) + (v.z > 0.5f) + (v.w > 0.5f);
    }
    #pragma unroll
    for (int o = 16; o; o >>= 1) cnt += __shfl_down_sync(0xFFFFFFFFu, cnt, o);
    __shared__ int sm[8];
    if ((threadIdx.x & 31) == 0) sm[threadIdx.x >> 5] = cnt;
    __syncthreads();
    if (threadIdx.x == 0) {
        int t = 0;
        #pragma unroll
        for (int j = 0; j < 8; j++) t += sm[j];
        atomicAdd(&g_nvalid[b], t);
    }
}

// ---------------------------------------------------------------------------
// k2: scatter — for each source pixel p=(h,w), compute integer target cell,
//     atomicMax the source linear index (last-in-row-major-order wins).
//     Empty cells keep key 0, which is exactly equivalent to source (0,0).
// ---------------------------------------------------------------------------
__global__ void k_scatter(const float* __restrict__ grid,
                          const float* __restrict__ seg) {
    int idx = blockIdx.x * blockDim.x + threadIdx.x;
    if (idx >= NTOT) return;
    int b = idx >> 16;          // / NPX
    int p = idx & 0xFFFF;       // h*256 + w

    bool fb = (__ldg(&g_nvalid[b]) == 0);
    bool m  = fb || (__ldg(&seg[idx]) > 0.5f);

    size_t gb = (size_t)b * 2 * NPX + p;
    float gx = __ldg(&grid[gb]);
    float gy = __ldg(&grid[gb + NPX]);
    float fx = m ? gx : 0.0f;
    float fy = m ? gy : 0.0f;

    // exact power-of-2 scaling: ((f+1)*0.5)*256, trunc toward zero, clip
    int ix = (int)(((fx + 1.0f) * 0.5f) * 256.0f);
    int iy = (int)(((fy + 1.0f) * 0.5f) * 256.0f);
    ix = min(max(ix, 0), HW - 1);
    iy = min(max(iy, 0), HW - 1);

    atomicMax(&g_keys[(b << 16) + (iy << 8) + ix], p);
}

// ---------------------------------------------------------------------------
// k3: gather + write outputs.
//     key -> winner (h,w); nearest-sample index = (h & ~1, w & ~1)
//     (round-half-to-even of v-0.5 == v & ~1; empty cell == key 0 == (0,0)).
// ---------------------------------------------------------------------------
__global__ void k_gather(const float* __restrict__ seg,
                         const float* __restrict__ conf,
                         const float* __restrict__ depth,
                         float* __restrict__ out) {
    int idx = blockIdx.x * blockDim.x + threadIdx.x;
    if (idx >= NTOT) return;
    int b = idx >> 16;
    int p = idx & 0xFFFF;

    int key = g_keys[idx];
    int sx = (key & 255) & ~1;          // sampled column
    int sy = (key >> 8)  & ~1;          // sampled row
    int sidx = (b << 16) + (sy << 8) + sx;

    bool fb = (__ldg(&g_nvalid[b]) == 0);
    float m = (fb || __ldg(&seg[sidx]) > 0.5f) ? 1.0f : 0.0f;
    float d = __ldg(&depth[sidx]);
    float c = __ldg(&conf[sidx]);

    float mx = (float)sx / 280.0f;
    float my = (float)sy / 280.0f;

    float* dk = out;                                     // [BS,3,HW,HW]
    float* cf = out + (size_t)BS * 3 * NPX;              // [BS,1,HW,HW]
    float* mk = cf  + (size_t)BS * NPX;                  // [BS,HW,HW]

    size_t db = (size_t)b * 3 * NPX + p;
    dk[db]            = mx * m;
    dk[db + NPX]      = my * m;
    dk[db + 2 * NPX]  = d * m;
    cf[idx] = c;
    mk[idx] = m;
}

// ---------------------------------------------------------------------------
extern "C" void kernel_launch(void* const* d_in, const int* in_sizes, int n_in,
                              void* d_out, int out_size) {
    const float* grid    = (const float*)d_in[0];
    const float* seg     = (const float*)d_in[1];
    const float* conf_is = (const float*)d_in[2];
    const float* depth   = (const float*)d_in[3];
    float* out = (float*)d_out;

    (void)in_sizes; (void)n_in; (void)out_size;

    k_zero<<<(NTOT / 4 + 255) / 256, 256>>>();
    k_count<<<BS * 8, 256>>>(seg);
    k_scatter<<<(NTOT + 255) / 256, 256>>>(grid, seg);
    k_gather<<<(NTOT + 255) / 256, 256>>>(seg, conf_is, depth, out);
}

// round 3
// speedup vs baseline: 5.1607x; 5.1607x over previous
#include <cuda_runtime.h>
#include <cstdint>

#define BS   128
#define HW   256
#define NPX  (HW * HW)          // 65536
#define NTOT (BS * NPX)         // 8,388,608

// Scratch: scatter keys (winner = max linear source index h*256+w) and per-batch
// valid-pixel counts for the all-True mask fallback.
__device__ int g_keys[NTOT];          // 33.5 MB
__device__ int g_nvalid[BS];

// ---------------------------------------------------------------------------
// k0: fused zero(keys,nvalid) + per-batch count of seg > 0.5
//     8192 blocks x 256 thr; each thread zeroes one int4 (4 keys) and counts
//     the matching 4 seg elements. Block spans 1024 px, all in one batch.
// ---------------------------------------------------------------------------
__global__ void k_zero_count(const float* __restrict__ seg) {
    int i = blockIdx.x * blockDim.x + threadIdx.x;        // int4 index
    reinterpret_cast<int4*>(g_keys)[i] = make_int4(0, 0, 0, 0);

    float4 v = reinterpret_cast<const float4*>(seg)[i];
    int cnt = (v.x > 0.5f) + (v.y > 0.5f) + (v.z > 0.5f) + (v.w > 0.5f);
    #pragma unroll
    for (int o = 16; o; o >>= 1) cnt += __shfl_down_sync(0xFFFFFFFFu, cnt, o);

    __shared__ int sm[8];
    if ((threadIdx.x & 31) == 0) sm[threadIdx.x >> 5] = cnt;
    __syncthreads();
    if (threadIdx.x == 0) {
        int t = 0;
        #pragma unroll
        for (int j = 0; j < 8; j++) t += sm[j];
        int b = (i * 4) >> 16;
        atomicAdd(&g_nvalid[b], t);
    }
}

// ---------------------------------------------------------------------------
// k2: scatter. Valid pixels: individual spread atomicMax. Masked pixels all
//     target (b,128,128); their winner is max(p), computed per-warp with
//     ballot (p contiguous) and per-block in smem -> ONE atomic per block,
//     killing the same-address contention chain.
// ---------------------------------------------------------------------------
__global__ void k_scatter(const float* __restrict__ grid,
                          const float* __restrict__ seg) {
    int idx = blockIdx.x * blockDim.x + threadIdx.x;
    int b = idx >> 16;          // / NPX  (constant per block: 256 | NPX)
    int p = idx & 0xFFFF;       // h*256 + w

    bool fb = (__ldg(&g_nvalid[b]) == 0);
    bool m  = fb || (__ldg(&seg[idx]) > 0.5f);

    size_t gb = (size_t)b * 2 * NPX + p;
    float gx = __ldg(&grid[gb]);
    float gy = __ldg(&grid[gb + NPX]);

    // --- masked pixels: dedupe to one atomic per block -----------------
    unsigned bal = __ballot_sync(0xFFFFFFFFu, !m);
    __shared__ int smax[8];
    int wid = threadIdx.x >> 5;
    if ((threadIdx.x & 31) == 0) {
        int warp_base = p & ~31;   // p of lane 0 in this warp
        smax[wid] = bal ? (warp_base + 31 - __clz(bal)) : -1;
    }
    __syncthreads();
    if (threadIdx.x == 0) {
        int mx = -1;
        #pragma unroll
        for (int j = 0; j < 8; j++) mx = max(mx, smax[j]);
        if (mx >= 0)
            atomicMax(&g_keys[(b << 16) + (128 << 8) + 128], mx);
    }

    // --- valid pixels: spread atomics -----------------------------------
    if (m) {
        // exact power-of-2 scaling: ((f+1)*0.5)*256, trunc toward zero, clip
        int ix = (int)(((gx + 1.0f) * 0.5f) * 256.0f);
        int iy = (int)(((gy + 1.0f) * 0.5f) * 256.0f);
        ix = min(max(ix, 0), HW - 1);
        iy = min(max(iy, 0), HW - 1);
        atomicMax(&g_keys[(b << 16) + (iy << 8) + ix], p);
    }
}

// ---------------------------------------------------------------------------
// k3: gather + write outputs, 4 px per thread (int4 keys, float4 stores).
//     key -> winner (h,w); nearest-sample index = (h & ~1, w & ~1)
//     (round-half-to-even of v-0.5 == v & ~1; empty cell == key 0 == (0,0)).
// ---------------------------------------------------------------------------
__global__ void k_gather(const float* __restrict__ seg,
                         const float* __restrict__ conf,
                         const float* __restrict__ depth,
                         float* __restrict__ out) {
    int t = blockIdx.x * blockDim.x + threadIdx.x;    // int4 index
    if (t >= NTOT / 4) return;
    int idx0 = t * 4;
    int b = idx0 >> 16;

    int4 key = reinterpret_cast<const int4*>(g_keys)[t];
    bool fb = (__ldg(&g_nvalid[b]) == 0);

    float4 vmx, vmy, vd, vc, vm;
    int keys[4] = {key.x, key.y, key.z, key.w};
    float rmx[4], rmy[4], rd[4], rc[4], rm[4];
    #pragma unroll
    for (int j = 0; j < 4; j++) {
        int k  = keys[j];
        int sx = (k & 255) & ~1;
        int sy = ((k >> 8) & 255) & ~1;
        int sidx = (b << 16) + (sy << 8) + sx;
        float m = (fb || __ldg(&seg[sidx]) > 0.5f) ? 1.0f : 0.0f;
        rd[j] = __ldg(&depth[sidx]) * m;
        rc[j] = __ldg(&conf[sidx]);
        rmx[j] = (float)sx * (1.0f / 280.0f) * m;
        rmy[j] = (float)sy * (1.0f / 280.0f) * m;
        rm[j] = m;
    }
    vmx = make_float4(rmx[0], rmx[1], rmx[2], rmx[3]);
    vmy = make_float4(rmy[0], rmy[1], rmy[2], rmy[3]);
    vd  = make_float4(rd[0],  rd[1],  rd[2],  rd[3]);
    vc  = make_float4(rc[0],  rc[1],  rc[2],  rc[3]);
    vm  = make_float4(rm[0],  rm[1],  rm[2],  rm[3]);

    float* dk = out;                                     // [BS,3,HW,HW]
    float* cf = out + (size_t)BS * 3 * NPX;              // [BS,1,HW,HW]
    float* mk = cf  + (size_t)BS * NPX;                  // [BS,HW,HW]

    int p0 = idx0 & 0xFFFF;
    size_t db4 = ((size_t)b * 3 * NPX + p0) >> 2;        // float4 index
    reinterpret_cast<float4*>(dk)[db4]                 = vmx;
    reinterpret_cast<float4*>(dk)[db4 + NPX / 4]       = vmy;
    reinterpret_cast<float4*>(dk)[db4 + 2 * (NPX / 4)] = vd;
    reinterpret_cast<float4*>(cf)[t] = vc;
    reinterpret_cast<float4*>(mk)[t] = vm;
}

// ---------------------------------------------------------------------------
extern "C" void kernel_launch(void* const* d_in, const int* in_sizes, int n_in,
                              void* d_out, int out_size) {
    const float* grid    = (const float*)d_in[0];
    const float* seg     = (const float*)d_in[1];
    const float* conf_is = (const float*)d_in[2];
    const float* depth   = (const float*)d_in[3];
    float* out = (float*)d_out;

    (void)in_sizes; (void)n_in; (void)out_size;

    cudaMemsetAsync(g_nvalid, 0, sizeof(int) * BS);
    k_zero_count<<<NTOT / 4 / 256, 256>>>(seg);
    k_scatter<<<NTOT / 256, 256>>>(grid, seg);
    k_gather<<<(NTOT / 4 + 255) / 256, 256>>>(seg, conf_is, depth, out);
}